// round 2
// baseline (speedup 1.0000x reference)
#include <cuda_runtime.h>
#include <cuda_bf16.h>
#include <cstdint>

// LogicLayer: out[i,j] = g_a(x[i,idx_a[j]]) * g_b(x[i,idx_b[j]])
// where g(v) = (logit > 0) ? 1-v : v   (sigmoid(l)>0.5 <=> l>0)
//
// Strategy:
//  - prep kernel packs (flag_a | idx_a(15b) | flag_b | idx_b(15b)) into one u32/j
//  - main kernel: 1 CTA per batch row, stages the 128 KiB x-row into smem
//    (coalesced float4), then random-gathers from smem (LDS).
//
// NOTE: idx arrays are int32 on the wire (JAX x64 disabled downcasts int64).

#define IN_DIM  32768
#define OUT_DIM 32768
#define BATCH   1024

__device__ uint32_t g_packed[OUT_DIM];

__global__ void prep_kernel(const float* __restrict__ logits,
                            const int* __restrict__ idx_a,
                            const int* __restrict__ idx_b) {
    int j = blockIdx.x * blockDim.x + threadIdx.x;
    if (j >= OUT_DIM) return;
    uint32_t ia = (uint32_t)idx_a[j] & 0x7FFFu;
    uint32_t ib = (uint32_t)idx_b[j] & 0x7FFFu;
    uint32_t fa = (logits[2 * j]     > 0.0f) ? 1u : 0u;
    uint32_t fb = (logits[2 * j + 1] > 0.0f) ? 1u : 0u;
    g_packed[j] = (fa << 31) | (ia << 16) | (fb << 15) | ib;
}

__device__ __forceinline__ float gate_eval(uint32_t p, const float* __restrict__ sx) {
    uint32_t ia = (p >> 16) & 0x7FFFu;
    uint32_t ib = p & 0x7FFFu;
    float a = sx[ia];
    float b = sx[ib];
    if (p & 0x80000000u) a = 1.0f - a;
    if (p & 0x00008000u) b = 1.0f - b;
    return a * b;
}

__global__ __launch_bounds__(1024, 1)
void logic_layer_kernel(const float* __restrict__ x,
                        float* __restrict__ out) {
    extern __shared__ float sx[];
    const int row = blockIdx.x;
    const float4* xr = reinterpret_cast<const float4*>(x + (size_t)row * IN_DIM);
    float4* sx4 = reinterpret_cast<float4*>(sx);

    // Stage row into smem, coalesced: 8192 float4 / 1024 threads = 8 each
    #pragma unroll
    for (int k = threadIdx.x; k < IN_DIM / 4; k += 1024) {
        sx4[k] = xr[k];
    }
    __syncthreads();

    float* orow = out + (size_t)row * OUT_DIM;

    #pragma unroll
    for (int base = 0; base < OUT_DIM; base += 1024 * 4) {
        int j = base + threadIdx.x * 4;
        uint4 p = *reinterpret_cast<const uint4*>(&g_packed[j]);
        float4 r;
        r.x = gate_eval(p.x, sx);
        r.y = gate_eval(p.y, sx);
        r.z = gate_eval(p.z, sx);
        r.w = gate_eval(p.w, sx);
        *reinterpret_cast<float4*>(&orow[j]) = r;
    }
}

extern "C" void kernel_launch(void* const* d_in, const int* in_sizes, int n_in,
                              void* d_out, int out_size) {
    const float* x      = (const float*)d_in[0];
    const float* logits = (const float*)d_in[1];
    const int*   idx_a  = (const int*)d_in[2];
    const int*   idx_b  = (const int*)d_in[3];
    float* out = (float*)d_out;

    cudaFuncSetAttribute(logic_layer_kernel,
                         cudaFuncAttributeMaxDynamicSharedMemorySize,
                         IN_DIM * (int)sizeof(float));

    prep_kernel<<<(OUT_DIM + 255) / 256, 256>>>(logits, idx_a, idx_b);
    logic_layer_kernel<<<BATCH, 1024, IN_DIM * sizeof(float)>>>(x, out);
}

// round 3
// speedup vs baseline: 1.0463x; 1.0463x over previous
#include <cuda_runtime.h>
#include <cstdint>

// LogicLayer: out[i,j] = g_a(x[i,idx_a[j]]) * g_b(x[i,idx_b[j]])
//   g(v) = (logit > 0) ? 1-v : v
//
// R3 changes vs R2 (92.6us, L1=76% smem-bound):
//  - prep_balance: per 32-j gather group, greedily swap (a,b) operand halves
//    (product is commutative) to balance smem banks across the two LDS
//    instructions -> conflict degree ~3.3 -> ~2.5, zero runtime cost.
//  - TMA bulk staging of the 128KiB x-row (no LDG/STS wavefronts, mbarrier wait).
//  - scalar j = k*1024 + t layout: gather groups are contiguous 32-j runs
//    matching prep_balance's grouping; stores stay fully coalesced.

#define IN_DIM   32768
#define OUT_DIM  32768
#define BATCH    1024
#define NTHREADS 1024
#define ITERS    (OUT_DIM / NTHREADS)  // 32

__device__ uint32_t g_packed[OUT_DIM];

// ---------------- prep 1: pack (fa|ia | fb|ib) into one u32 per j -------------
__global__ void prep_pack(const float* __restrict__ logits,
                          const int* __restrict__ idx_a,
                          const int* __restrict__ idx_b) {
    int j = blockIdx.x * blockDim.x + threadIdx.x;
    if (j >= OUT_DIM) return;
    uint32_t ia = (uint32_t)idx_a[j] & 0x7FFFu;
    uint32_t ib = (uint32_t)idx_b[j] & 0x7FFFu;
    uint32_t fa = (logits[2 * j]     > 0.0f) ? 1u : 0u;
    uint32_t fb = (logits[2 * j + 1] > 0.0f) ? 1u : 0u;
    // hi16 = (fa<<15)|ia, lo16 = (fb<<15)|ib  -> operand swap == 16-bit rotate
    g_packed[j] = (fa << 31) | (ia << 16) | (fb << 15) | ib;
}

// ---------------- prep 2: per-group operand-swap bank balancing ---------------
// Gather group = 32 consecutive j's (one warp iteration in the main kernel).
// LDS#1 reads the hi16 operand of each lane, LDS#2 the lo16 operand.
// Greedily choose per-lane swap to minimize per-instruction max bank load.
// Counters: 32 banks x 4-bit saturating nibbles packed in 2x u64 per instr.
__device__ __forceinline__ uint32_t nib_get(uint64_t lo, uint64_t hi, uint32_t b) {
    uint64_t w = (b < 16) ? lo : hi;
    return (uint32_t)(w >> ((b & 15u) * 4)) & 15u;
}
__device__ __forceinline__ void nib_inc(uint64_t& lo, uint64_t& hi, uint32_t b) {
    uint32_t cur = nib_get(lo, hi, b);
    if (cur >= 15u) return;  // saturate
    uint64_t add = 1ull << ((b & 15u) * 4);
    if (b < 16) lo += add; else hi += add;
}

__global__ void prep_balance() {
    int g = blockIdx.x * blockDim.x + threadIdx.x;
    if (g >= OUT_DIM / 32) return;
    uint64_t c0lo = 0, c0hi = 0;  // bank loads of LDS#1 (hi16 operands)
    uint64_t c1lo = 0, c1hi = 0;  // bank loads of LDS#2 (lo16 operands)
    const int base = g * 32;
    #pragma unroll 4
    for (int l = 0; l < 32; l++) {
        uint32_t p  = g_packed[base + l];
        uint32_t ba = (p >> 16) & 31u;  // bank of hi operand
        uint32_t bb = p & 31u;          // bank of lo operand
        uint32_t costA = max(nib_get(c0lo, c0hi, ba), nib_get(c1lo, c1hi, bb));
        uint32_t costB = max(nib_get(c0lo, c0hi, bb), nib_get(c1lo, c1hi, ba));
        if (costB < costA) {
            g_packed[base + l] = __funnelshift_l(p, p, 16);  // swap operands
            nib_inc(c0lo, c0hi, bb);
            nib_inc(c1lo, c1hi, ba);
        } else {
            nib_inc(c0lo, c0hi, ba);
            nib_inc(c1lo, c1hi, bb);
        }
    }
}

// ---------------- main kernel: TMA-stage row, gather from smem ----------------
__device__ __forceinline__ uint32_t smem_u32(const void* p) {
    uint32_t a;
    asm("{ .reg .u64 t; cvta.to.shared.u64 t, %1; cvt.u32.u64 %0, t; }"
        : "=r"(a) : "l"(p));
    return a;
}

__global__ __launch_bounds__(NTHREADS, 1)
void logic_layer_kernel(const float* __restrict__ x,
                        float* __restrict__ out) {
    extern __shared__ float sx[];
    __shared__ __align__(8) uint64_t mbar;

    const int row = blockIdx.x;
    const uint32_t mbar_a = smem_u32(&mbar);
    const uint32_t dst_a  = smem_u32(sx);

    if (threadIdx.x == 0) {
        asm volatile("mbarrier.init.shared.b64 [%0], 1;" :: "r"(mbar_a) : "memory");
        asm volatile("fence.proxy.async.shared::cta;" ::: "memory");
    }
    __syncthreads();

    if (threadIdx.x == 0) {
        asm volatile("mbarrier.arrive.expect_tx.shared.b64 _, [%0], %1;"
                     :: "r"(mbar_a), "r"((uint32_t)(IN_DIM * 4)) : "memory");
        asm volatile("cp.async.bulk.shared::cta.global.mbarrier::complete_tx::bytes "
                     "[%0], [%1], %2, [%3];"
                     :: "r"(dst_a), "l"(x + (size_t)row * IN_DIM),
                        "r"((uint32_t)(IN_DIM * 4)), "r"(mbar_a)
                     : "memory");
    }

    // wait for the row to land (acquire orders subsequent LDS)
    {
        uint32_t done;
        asm volatile(
            "{\n\t.reg .pred P;\n\t"
            "mbarrier.try_wait.parity.acquire.cta.shared::cta.b64 P, [%1], 0, 0x989680;\n\t"
            "selp.b32 %0, 1, 0, P;\n\t}"
            : "=r"(done) : "r"(mbar_a) : "memory");
        if (!done) {
            asm volatile(
                "{\n\t.reg .pred P;\n"
                "WL_%=:\n\t"
                "mbarrier.try_wait.parity.acquire.cta.shared::cta.b64 P, [%0], 0, 0x989680;\n\t"
                "@P bra.uni WD_%=;\n\t"
                "bra.uni WL_%=;\n"
                "WD_%=:\n\t}"
                :: "r"(mbar_a) : "memory");
        }
    }

    float* orow = out + (size_t)row * OUT_DIM;
    const int t = threadIdx.x;

    #pragma unroll 8
    for (int k = 0; k < ITERS; k++) {
        int j = k * NTHREADS + t;
        uint32_t p = g_packed[j];
        float a = sx[(p >> 16) & 0x7FFFu];
        float b = sx[p & 0x7FFFu];
        if (p & 0x80000000u) a = 1.0f - a;
        if (p & 0x00008000u) b = 1.0f - b;
        orow[j] = a * b;
    }
}

extern "C" void kernel_launch(void* const* d_in, const int* in_sizes, int n_in,
                              void* d_out, int out_size) {
    const float* x      = (const float*)d_in[0];
    const float* logits = (const float*)d_in[1];
    const int*   idx_a  = (const int*)d_in[2];
    const int*   idx_b  = (const int*)d_in[3];
    float* out = (float*)d_out;

    cudaFuncSetAttribute(logic_layer_kernel,
                         cudaFuncAttributeMaxDynamicSharedMemorySize,
                         IN_DIM * (int)sizeof(float));

    prep_pack<<<(OUT_DIM + 255) / 256, 256>>>(logits, idx_a, idx_b);
    prep_balance<<<(OUT_DIM / 32 + 255) / 256, 256>>>();
    logic_layer_kernel<<<BATCH, NTHREADS, IN_DIM * sizeof(float)>>>(x, out);
}